// round 8
// baseline (speedup 1.0000x reference)
#include <cuda_runtime.h>
#include <cuda_bf16.h>
#include <cstdint>
#include <math.h>

// ---------------- problem constants ----------------
#define BB     64
#define D0     4096
#define D1     1024
#define D2OUT  1000
#define TT     32
#define MROWS  (BB * TT)          // 2048 GEMM rows
#define DELTA  1e-3f              // borderline-gap threshold for exact fix-up

// ---------------- device scratch (static globals; no runtime alloc) ----------------
__device__ __nv_bfloat16 g_Bh[(size_t)D0 * D0];
__device__ __nv_bfloat16 g_Bm[(size_t)D0 * D0];
__device__ __nv_bfloat16 g_Bl[(size_t)D0 * D0];
__device__ __nv_bfloat16 g_B2h[(size_t)D1 * D1];   // rows >= 1000 never written -> stay zero
__device__ __nv_bfloat16 g_B2m[(size_t)D1 * D1];
__device__ __nv_bfloat16 g_B2l[(size_t)D1 * D1];
__device__ __nv_bfloat16 g_A[(size_t)MROWS * D0];  // spike matrix (ld = 4096 for L0, 1024 for L2)
__device__ int           g_cnt0[BB * D0];
__device__ unsigned char g_N1[BB * D1];
__device__ int           g_cnt2[BB * D2OUT];
__device__ unsigned char g_flag0[BB * D0];
__device__ unsigned char g_flag2[BB * D2OUT];
__device__ uint32_t      g_ord0[BB * D0];
__device__ int           g_seg0[BB * 34];
__device__ uint32_t      g_ord2[BB * D1];
__device__ int           g_seg2[BB * 34];

// ---------------- PTX helpers (base sm_103-legal only) ----------------
__device__ __forceinline__ uint32_t smem_u32(const void* p) {
    uint32_t a;
    asm("{ .reg .u64 t; cvta.to.shared.u64 t, %1; cvt.u32.u64 %0, t; }" : "=r"(a) : "l"(p));
    return a;
}
#define CP_ASYNC16(dst, src) \
    asm volatile("cp.async.cg.shared.global [%0], [%1], 16;" :: "r"(dst), "l"(src) : "memory")
#define CP_COMMIT() asm volatile("cp.async.commit_group;" ::: "memory")
#define CP_WAIT1()  asm volatile("cp.async.wait_group 1;" ::: "memory")
#define CP_WAIT0()  asm volatile("cp.async.wait_group 0;" ::: "memory")
#define LDSM4(r0, r1, r2, r3, addr)                                              \
    asm volatile("ldmatrix.sync.aligned.m8n8.x4.shared.b16 {%0,%1,%2,%3}, [%4];" \
                 : "=r"(r0), "=r"(r1), "=r"(r2), "=r"(r3) : "r"(addr))
#define MMA16816(d, a, b0, b1)                                                      \
    asm volatile("mma.sync.aligned.m16n8k16.row.col.f32.bf16.bf16.f32 "             \
                 "{%0,%1,%2,%3},{%4,%5,%6,%7},{%8,%9},{%0,%1,%2,%3};"               \
                 : "+f"((d)[0]), "+f"((d)[1]), "+f"((d)[2]), "+f"((d)[3])           \
                 : "r"((a)[0]), "r"((a)[1]), "r"((a)[2]), "r"((a)[3]),              \
                   "r"(b0), "r"(b1))
#define SWZ128(off) ((off) ^ (((off) >> 3) & 0x70))

// ---------------- uniform spike pattern (reference fp32 semantics) ----------------
__device__ __forceinline__ uint32_t pattern_mask(int n) {
    if (n <= 0)  return 0u;
    if (n >= TT) return 0xFFFFFFFFu;
    float spacing = __fdiv_rn(32.0f, (float)n);
    uint32_t m = 0u;
    for (int c = 0; c < TT; c++) {
        double r = fmod((double)c, (double)spacing);
        if (r < 1.0) m |= (1u << c);
    }
    return m;
}

// ---------------- weight splits: w = hi + mid + lo ----------------
__global__ void split0_kernel(const float* __restrict__ w) {
    size_t idx = (size_t)blockIdx.x * 256 + threadIdx.x;
    float wv = w[idx];
    __nv_bfloat16 h = __float2bfloat16(wv);
    float r1 = wv - __bfloat162float(h);
    __nv_bfloat16 m = __float2bfloat16(r1);
    float r2 = r1 - __bfloat162float(m);
    g_Bh[idx] = h; g_Bm[idx] = m; g_Bl[idx] = __float2bfloat16(r2);
}
__global__ void split2_kernel(const float* __restrict__ w) {
    size_t idx = (size_t)blockIdx.x * 256 + threadIdx.x;   // covers 1000*1024 exactly
    float wv = w[idx];
    __nv_bfloat16 h = __float2bfloat16(wv);
    float r1 = wv - __bfloat162float(h);
    __nv_bfloat16 m = __float2bfloat16(r1);
    float r2 = r1 - __bfloat162float(m);
    g_B2h[idx] = h; g_B2m[idx] = m; g_B2l[idx] = __float2bfloat16(r2);
}

// ---------------- spike-matrix builds ----------------
__global__ void buildA0_kernel(const float* __restrict__ x, const int* __restrict__ idx0) {
    __shared__ uint32_t spat[33];
    int tid = threadIdx.x;
    if (tid < 33) spat[tid] = pattern_mask(tid);
    __syncthreads();
    int b = blockIdx.y;
    int i = blockIdx.x * 256 + tid;
    float r = x[b * D0 + idx0[i]];
    uint32_t m = spat[__float2int_rn(r * 32.0f)];
    unsigned short* A = (unsigned short*)g_A;
#pragma unroll
    for (int t = 0; t < TT; t++)
        A[(size_t)(b * TT + t) * D0 + i] = ((m >> t) & 1u) ? (unsigned short)0x3F80 : (unsigned short)0;
}
__global__ void buildA2_kernel(const int* __restrict__ idx2) {
    __shared__ uint32_t spat[33];
    int tid = threadIdx.x;
    if (tid < 33) spat[tid] = pattern_mask(tid);
    __syncthreads();
    int b = blockIdx.y;
    int i = blockIdx.x * 256 + tid;
    uint32_t m = spat[g_N1[b * D1 + idx2[i]]];
    unsigned short* A = (unsigned short*)g_A;
#pragma unroll
    for (int t = 0; t < TT; t++)
        A[(size_t)(b * TT + t) * D1 + i] = ((m >> t) & 1u) ? (unsigned short)0x3F80 : (unsigned short)0;
}

// ---------------- deterministic warp counting sort (verbatim R1) ----------------
__device__ void counting_sort_warp(const unsigned char* ns, int K,
                                   uint32_t* ord_out, int* seg_out) {
    int lane = threadIdx.x;
    int per = K >> 5;
    int lc[33];
    for (int n = 0; n < 33; n++) lc[n] = 0;
    for (int c = 0; c < per; c++) lc[ns[lane * per + c]]++;
    int off[33];
    int base = 0;
    for (int n = 0; n < 33; n++) {
        int v = lc[n];
        int s = v;
#pragma unroll
        for (int d = 1; d < 32; d <<= 1) {
            int o = __shfl_up_sync(0xffffffffu, s, d);
            if (lane >= d) s += o;
        }
        int tot = __shfl_sync(0xffffffffu, s, 31);
        off[n] = base + s - v;
        if (lane == 0) seg_out[n] = base;
        base += tot;
    }
    if (lane == 0) seg_out[33] = base;
    for (int c = 0; c < per; c++) {
        int i = lane * per + c;
        int n = ns[i];
        ord_out[off[n]++] = (uint32_t)i;
    }
}
__global__ void sort1_kernel(const float* __restrict__ x, const int* __restrict__ idx0) {
    __shared__ unsigned char ns[D0];
    int b = blockIdx.x, lane = threadIdx.x;
    for (int i = lane; i < D0; i += 32) {
        float r = x[b * D0 + idx0[i]];
        ns[i] = (unsigned char)__float2int_rn(r * 32.0f);
    }
    __syncwarp();
    counting_sort_warp(ns, D0, g_ord0 + b * D0, g_seg0 + b * 34);
}
__global__ void sort2_kernel(const int* __restrict__ idx2) {
    __shared__ unsigned char ns[D1];
    int b = blockIdx.x, lane = threadIdx.x;
    for (int i = lane; i < D1; i += 32) {
        ns[i] = g_N1[b * D1 + idx2[i]];
    }
    __syncwarp();
    counting_sort_warp(ns, D1, g_ord2 + b * D1, g_seg2 + b * 34);
}

// ---------------- GEMM + fused LIF scan + borderline flagging ----------------
template <int L>
__global__ void __launch_bounds__(256, 1) gemm_lif_kernel(const float* __restrict__ thr_p) {
    constexpr int KTOT = (L == 0) ? D0 : D1;
    constexpr int NC   = KTOT / 64;
    constexpr int JMAX = (L == 0) ? D0 : D2OUT;

    extern __shared__ char smem[];
    uint32_t sb = smem_u32(smem);
    int tid = threadIdx.x, wid = tid >> 5, lane = tid & 31;
    int n0 = blockIdx.x * 128, m0 = blockIdx.y * 128;
    int wm = wid >> 1, wn = wid & 1;
    const int mW = wm * 32, nW = wn * 64;

    const __nv_bfloat16* Bs[3];
    if (L == 0) { Bs[0] = g_Bh; Bs[1] = g_Bm; Bs[2] = g_Bl; }
    else        { Bs[0] = g_B2h; Bs[1] = g_B2m; Bs[2] = g_B2l; }

    auto load_stage = [&](int stage, int kc) {
        uint32_t st = sb + (uint32_t)stage * 65536u;
        int k0 = kc * 64;
#pragma unroll
        for (int u = 0; u < 4; u++) {
            int slot = u * 256 + tid, r = slot >> 3, kk = slot & 7;
            const __nv_bfloat16* gp = g_A + (size_t)(m0 + r) * KTOT + k0 + kk * 8;
            uint32_t off = (uint32_t)(r * 128 + kk * 16);
            CP_ASYNC16(st + SWZ128(off), gp);
        }
#pragma unroll
        for (int s = 0; s < 3; s++) {
            uint32_t bb = st + 16384u * (1 + s);
#pragma unroll
            for (int u = 0; u < 4; u++) {
                int slot = u * 256 + tid, r = slot >> 3, kk = slot & 7;
                const __nv_bfloat16* gp = Bs[s] + (size_t)(n0 + r) * KTOT + k0 + kk * 8;
                uint32_t off = (uint32_t)(r * 128 + kk * 16);
                CP_ASYNC16(bb + SWZ128(off), gp);
            }
        }
        CP_COMMIT();
    };

    float acc[2][8][4];
#pragma unroll
    for (int a = 0; a < 2; a++)
#pragma unroll
        for (int b = 0; b < 8; b++)
#pragma unroll
            for (int c = 0; c < 4; c++) acc[a][b][c] = 0.f;

    int q = lane >> 3, w8 = lane & 7;

    load_stage(0, 0);
#pragma unroll 1
    for (int c = 0; c < NC; c++) {
        if (c + 1 < NC) { load_stage((c + 1) & 1, c + 1); CP_WAIT1(); }
        else            { CP_WAIT0(); }
        __syncthreads();

        uint32_t st = sb + (uint32_t)(c & 1) * 65536u;
#pragma unroll
        for (int ks = 0; ks < 4; ks++) {
            uint32_t af[2][4];
#pragma unroll
            for (int mf = 0; mf < 2; mf++) {
                int row = mW + mf * 16 + w8 + (q & 1) * 8;
                int colb = ks * 32 + (q >> 1) * 16;
                LDSM4(af[mf][0], af[mf][1], af[mf][2], af[mf][3],
                      st + SWZ128((uint32_t)(row * 128 + colb)));
            }
#pragma unroll
            for (int s = 0; s < 3; s++) {
                uint32_t bbase = st + 16384u * (1 + s);
#pragma unroll
                for (int nfp = 0; nfp < 4; nfp++) {
                    uint32_t b0, b1, b2, b3;
                    int row = nW + nfp * 16 + w8 + (q >> 1) * 8;
                    int colb = ks * 32 + (q & 1) * 16;
                    LDSM4(b0, b1, b2, b3, bbase + SWZ128((uint32_t)(row * 128 + colb)));
                    MMA16816(acc[0][2 * nfp + 0], af[0], b0, b1);
                    MMA16816(acc[0][2 * nfp + 1], af[0], b2, b3);
                    MMA16816(acc[1][2 * nfp + 0], af[1], b0, b1);
                    MMA16816(acc[1][2 * nfp + 1], af[1], b2, b3);
                }
            }
        }
        __syncthreads();
    }

    // ---- epilogue: transpose C through padded smem tile, LIF scan + gap flag ----
    float* ct = (float*)smem;                         // [128][129] fp32
#pragma unroll
    for (int mf = 0; mf < 2; mf++)
#pragma unroll
        for (int nf = 0; nf < 8; nf++) {
            int row = mW + mf * 16 + (lane >> 2);
            int col = nW + nf * 8 + 2 * (lane & 3);
            ct[row * 129 + col]           = acc[mf][nf][0];
            ct[row * 129 + col + 1]       = acc[mf][nf][1];
            ct[(row + 8) * 129 + col]     = acc[mf][nf][2];
            ct[(row + 8) * 129 + col + 1] = acc[mf][nf][3];
        }
    __syncthreads();

    float thr = *thr_p;
    int* cnt_out = (L == 0) ? g_cnt0 : g_cnt2;
    unsigned char* flag_out = (L == 0) ? g_flag0 : g_flag2;
#pragma unroll
    for (int pp = 0; pp < 2; pp++) {
        int p = pp * 256 + tid;
        int bl = p >> 7, j = p & 127;
        float memb = 0.f, ming = 1e30f;
        int cnt = 0;
#pragma unroll
        for (int t = 0; t < TT; t++) {
            memb += ct[(bl * 32 + t) * 129 + j];
            float g = fabsf(memb - thr);
            if (g < ming) ming = g;
            if (memb > thr) { memb -= thr; cnt++; }
        }
        int bglob = blockIdx.y * 4 + bl;
        int jglob = n0 + j;
        if (jglob < JMAX) {
            cnt_out[(size_t)bglob * JMAX + jglob] = cnt;
            flag_out[(size_t)bglob * JMAX + jglob] = (ming < DELTA) ? 1 : 0;
        }
    }
}

// ---------------- exact fix-up: replicate R1's bit-exact scalar path for flagged entries ----
template <int L>
__global__ void fixup_kernel(const float* __restrict__ w, const float* __restrict__ thr_p) {
    constexpr int K    = (L == 0) ? D0 : D1;
    constexpr int JMAX = (L == 0) ? D0 : D2OUT;
    __shared__ uint32_t spat[33];
    int tid = threadIdx.x;
    if (tid < 33) spat[tid] = pattern_mask(tid);
    __syncthreads();

    int b = blockIdx.y;
    int j = blockIdx.x * 256 + tid;
    if (j >= JMAX) return;
    const unsigned char* flag = (L == 0) ? g_flag0 : g_flag2;
    if (!flag[(size_t)b * JMAX + j]) return;

    const uint32_t* po = ((L == 0) ? g_ord0 : g_ord2) + b * K;
    const int*      sg = ((L == 0) ? g_seg0 : g_seg2) + b * 34;
    const float* wrow = w + (size_t)j * K;    // == R1's Wt[i*ld + j] values

    float I[TT];
#pragma unroll
    for (int t = 0; t < TT; t++) I[t] = 0.f;

#pragma unroll 1
    for (int n = 1; n < 33; n++) {
        int s = sg[n], e = sg[n + 1];
        if (s >= e) continue;
        float a0 = 0.f, a1 = 0.f, a2 = 0.f, a3 = 0.f;
        int k = s;
        float p0 = 0.f, p1 = 0.f, p2 = 0.f, p3 = 0.f;
        if (k + 4 <= e) {
            p0 = wrow[po[k]]; p1 = wrow[po[k + 1]];
            p2 = wrow[po[k + 2]]; p3 = wrow[po[k + 3]];
        }
#pragma unroll 1
        for (; k + 4 <= e; ) {
            float c0 = p0, c1 = p1, c2 = p2, c3 = p3;
            int kn = k + 4;
            if (kn + 4 <= e) {
                p0 = wrow[po[kn]]; p1 = wrow[po[kn + 1]];
                p2 = wrow[po[kn + 2]]; p3 = wrow[po[kn + 3]];
            }
            a0 += c0; a1 += c1; a2 += c2; a3 += c3;   // R1 add order
            k = kn;
        }
        for (; k < e; k++) a0 += wrow[po[k]];
        float acc = (a0 + a1) + (a2 + a3);
        uint32_t m = spat[n];
#pragma unroll
        for (int t = 0; t < TT; t++)
            if ((m >> t) & 1u) I[t] += acc;
    }

    float thr = *thr_p;
    float memb = 0.f;
    int cnt = 0;
#pragma unroll
    for (int t = 0; t < TT; t++) {
        memb += I[t];
        if (memb > thr) { memb -= thr; cnt++; }
    }
    if (L == 0) g_cnt0[b * D0 + j] = cnt; else g_cnt2[b * D2OUT + j] = cnt;
}

// ---------------- pooling + layer-1 re-encoding (exact integer/pow2 arithmetic) ----------------
__global__ void mid_kernel(const int* __restrict__ idx1) {
    int b = blockIdx.x, p = threadIdx.x;
    int ch = p >> 4, oh = (p >> 2) & 3, ow = p & 3;
    int c = 0;
#pragma unroll
    for (int dh = 0; dh < 2; dh++)
#pragma unroll
        for (int dw = 0; dw < 2; dw++) {
            int k = ch * 64 + (2 * oh + dh) * 8 + (2 * ow + dw);
            c += g_cnt0[b * D0 + idx1[k]];
        }
    g_N1[b * D1 + p] = (unsigned char)__float2int_rn((float)c * 0.25f);
}

// ---------------- output gather ----------------
__global__ void out_kernel(const int* __restrict__ idx_out, float* __restrict__ out) {
    int b = blockIdx.x, j = threadIdx.x;
    if (j < D2OUT) out[b * D2OUT + j] = (float)g_cnt2[b * D2OUT + idx_out[j]];
}

// ---------------- launch ----------------
extern "C" void kernel_launch(void* const* d_in, const int* in_sizes, int n_in,
                              void* d_out, int out_size) {
    (void)in_sizes; (void)n_in; (void)out_size;
    const float* x       = (const float*)d_in[0];
    const float* w0      = (const float*)d_in[1];
    const float* t0      = (const float*)d_in[2];
    const float* w2      = (const float*)d_in[3];
    const float* t2      = (const float*)d_in[4];
    const int*   idx0    = (const int*)d_in[5];
    const int*   idx1    = (const int*)d_in[6];
    const int*   idx2    = (const int*)d_in[7];
    const int*   idx_out = (const int*)d_in[8];
    float* out = (float*)d_out;

    const int SMEM_TOTAL = 2 * 65536;
    cudaFuncSetAttribute(gemm_lif_kernel<0>, cudaFuncAttributeMaxDynamicSharedMemorySize, SMEM_TOTAL);
    cudaFuncSetAttribute(gemm_lif_kernel<1>, cudaFuncAttributeMaxDynamicSharedMemorySize, SMEM_TOTAL);

    split0_kernel<<<(int)(((size_t)D0 * D0) / 256), 256>>>(w0);
    split2_kernel<<<(D2OUT * D1) / 256, 256>>>(w2);

    buildA0_kernel<<<dim3(D0 / 256, BB), 256>>>(x, idx0);
    sort1_kernel<<<BB, 32>>>(x, idx0);
    gemm_lif_kernel<0><<<dim3(D0 / 128, MROWS / 128), 256, SMEM_TOTAL>>>(t0);
    fixup_kernel<0><<<dim3(D0 / 256, BB), 256>>>(w0, t0);

    mid_kernel<<<BB, D1>>>(idx1);
    buildA2_kernel<<<dim3(D1 / 256, BB), 256>>>(idx2);
    sort2_kernel<<<BB, 32>>>(idx2);
    gemm_lif_kernel<1><<<dim3(D1 / 128, MROWS / 128), 256, SMEM_TOTAL>>>(t2);
    fixup_kernel<1><<<dim3(4, BB), 256>>>(w2, t2);

    out_kernel<<<BB, 1024>>>(idx_out, out);
}

// round 9
// speedup vs baseline: 1.2556x; 1.2556x over previous
#include <cuda_runtime.h>
#include <cuda_bf16.h>
#include <cstdint>
#include <math.h>

// ---------------- problem constants ----------------
#define BB     64
#define D0     4096
#define D1     1024
#define D2OUT  1000
#define TT     32
#define MROWS  (BB * TT)          // 2048 GEMM rows
#define DELTA  1e-3f              // borderline-gap threshold for exact fix-up

// ---------------- device scratch (static globals; no runtime alloc) ----------------
__device__ __nv_bfloat16 g_Bh[(size_t)D0 * D0];
__device__ __nv_bfloat16 g_Bm[(size_t)D0 * D0];
__device__ __nv_bfloat16 g_B2h[(size_t)D1 * D1];   // rows >= 1000 never written -> stay zero
__device__ __nv_bfloat16 g_B2m[(size_t)D1 * D1];
__device__ __nv_bfloat16 g_A[(size_t)MROWS * D0];  // spike matrix (ld = 4096 for L0, 1024 for L2)
__device__ int           g_cnt0[BB * D0];
__device__ unsigned char g_N1[BB * D1];
__device__ int           g_cnt2[BB * D2OUT];
__device__ unsigned char g_flag0[BB * D0];
__device__ unsigned char g_flag2[BB * D2OUT];
__device__ uint32_t      g_ord0[BB * D0];
__device__ int           g_seg0[BB * 34];
__device__ uint32_t      g_ord2[BB * D1];
__device__ int           g_seg2[BB * 34];

// ---------------- PTX helpers (base sm_103-legal only) ----------------
__device__ __forceinline__ uint32_t smem_u32(const void* p) {
    uint32_t a;
    asm("{ .reg .u64 t; cvta.to.shared.u64 t, %1; cvt.u32.u64 %0, t; }" : "=r"(a) : "l"(p));
    return a;
}
#define CP_ASYNC16(dst, src) \
    asm volatile("cp.async.cg.shared.global [%0], [%1], 16;" :: "r"(dst), "l"(src) : "memory")
#define CP_COMMIT() asm volatile("cp.async.commit_group;" ::: "memory")
#define CP_WAIT1()  asm volatile("cp.async.wait_group 1;" ::: "memory")
#define CP_WAIT0()  asm volatile("cp.async.wait_group 0;" ::: "memory")
#define LDSM4(r0, r1, r2, r3, addr)                                              \
    asm volatile("ldmatrix.sync.aligned.m8n8.x4.shared.b16 {%0,%1,%2,%3}, [%4];" \
                 : "=r"(r0), "=r"(r1), "=r"(r2), "=r"(r3) : "r"(addr))
#define MMA16816(d, a, b0, b1)                                                      \
    asm volatile("mma.sync.aligned.m16n8k16.row.col.f32.bf16.bf16.f32 "             \
                 "{%0,%1,%2,%3},{%4,%5,%6,%7},{%8,%9},{%0,%1,%2,%3};"               \
                 : "+f"((d)[0]), "+f"((d)[1]), "+f"((d)[2]), "+f"((d)[3])           \
                 : "r"((a)[0]), "r"((a)[1]), "r"((a)[2]), "r"((a)[3]),              \
                   "r"(b0), "r"(b1))
#define SWZ128(off) ((off) ^ (((off) >> 3) & 0x70))

// ---------------- uniform spike pattern (reference fp32 semantics) ----------------
__device__ __forceinline__ uint32_t pattern_mask(int n) {
    if (n <= 0)  return 0u;
    if (n >= TT) return 0xFFFFFFFFu;
    float spacing = __fdiv_rn(32.0f, (float)n);
    uint32_t m = 0u;
    for (int c = 0; c < TT; c++) {
        double r = fmod((double)c, (double)spacing);
        if (r < 1.0) m |= (1u << c);
    }
    return m;
}

// ---------------- weight splits: w = hi + mid (+ tiny residual handled by fix-up) ------
__global__ void split0_kernel(const float* __restrict__ w) {
    size_t idx = (size_t)blockIdx.x * 256 + threadIdx.x;
    float wv = w[idx];
    __nv_bfloat16 h = __float2bfloat16(wv);
    float r1 = wv - __bfloat162float(h);
    g_Bh[idx] = h; g_Bm[idx] = __float2bfloat16(r1);
}
__global__ void split2_kernel(const float* __restrict__ w) {
    size_t idx = (size_t)blockIdx.x * 256 + threadIdx.x;   // covers 1000*1024 exactly
    float wv = w[idx];
    __nv_bfloat16 h = __float2bfloat16(wv);
    float r1 = wv - __bfloat162float(h);
    g_B2h[idx] = h; g_B2m[idx] = __float2bfloat16(r1);
}

// ---------------- spike-matrix builds ----------------
__global__ void buildA0_kernel(const float* __restrict__ x, const int* __restrict__ idx0) {
    __shared__ uint32_t spat[33];
    int tid = threadIdx.x;
    if (tid < 33) spat[tid] = pattern_mask(tid);
    __syncthreads();
    int b = blockIdx.y;
    int i = blockIdx.x * 256 + tid;
    float r = x[b * D0 + idx0[i]];
    uint32_t m = spat[__float2int_rn(r * 32.0f)];
    unsigned short* A = (unsigned short*)g_A;
#pragma unroll
    for (int t = 0; t < TT; t++)
        A[(size_t)(b * TT + t) * D0 + i] = ((m >> t) & 1u) ? (unsigned short)0x3F80 : (unsigned short)0;
}
__global__ void buildA2_kernel(const int* __restrict__ idx2) {
    __shared__ uint32_t spat[33];
    int tid = threadIdx.x;
    if (tid < 33) spat[tid] = pattern_mask(tid);
    __syncthreads();
    int b = blockIdx.y;
    int i = blockIdx.x * 256 + tid;
    uint32_t m = spat[g_N1[b * D1 + idx2[i]]];
    unsigned short* A = (unsigned short*)g_A;
#pragma unroll
    for (int t = 0; t < TT; t++)
        A[(size_t)(b * TT + t) * D1 + i] = ((m >> t) & 1u) ? (unsigned short)0x3F80 : (unsigned short)0;
}

// ---------------- deterministic bucket sort (spill-free; ord = indices sorted by (n, i)) ----
// R1's lane-blocked stable counting sort over contiguous chunks produces exactly
// "sorted by (bucket, index ascending)". This reproduces identical ord/seg content with
// 128 threads and all dynamic-index arrays in shared memory (no local spills).
template <int K>
__global__ void sort_kernel(const float* __restrict__ x, const int* __restrict__ idxg) {
    __shared__ unsigned char ns[K];
    __shared__ int cnt[128 * 33];
    __shared__ int base[34];
    int b = blockIdx.x, t = threadIdx.x;
    constexpr int CH = K / 128;

    if (K == D0) {   // layer 0: encode from x
        for (int i = t; i < K; i += 128)
            ns[i] = (unsigned char)__float2int_rn(x[b * D0 + idxg[i]] * 32.0f);
    } else {         // layer 2: encode from N1
        for (int i = t; i < K; i += 128)
            ns[i] = g_N1[b * D1 + idxg[i]];
    }
#pragma unroll
    for (int n = 0; n < 33; n++) cnt[t * 33 + n] = 0;
    __syncthreads();
    for (int c = 0; c < CH; c++) cnt[t * 33 + ns[t * CH + c]]++;
    __syncthreads();
    if (t < 33) {            // per-bucket: exclusive prefix over chunks + total
        int run = 0;
        for (int u = 0; u < 128; u++) { int v = cnt[u * 33 + t]; cnt[u * 33 + t] = run; run += v; }
        base[t] = run;       // temporarily the total
    }
    __syncthreads();
    if (t == 0) {            // bucket bases
        int acc = 0;
        for (int n = 0; n < 33; n++) { int v = base[n]; base[n] = acc; acc += v; }
        base[33] = acc;
    }
    __syncthreads();
    uint32_t* ord = ((K == D0) ? g_ord0 : g_ord2) + (size_t)b * K;
    int* seg = ((K == D0) ? g_seg0 : g_seg2) + b * 34;
    for (int c = 0; c < CH; c++) {
        int i = t * CH + c;
        int n = ns[i];
        int pos = base[n] + cnt[t * 33 + n];
        cnt[t * 33 + n]++;
        ord[pos] = (uint32_t)i;
    }
    if (t < 34) seg[t] = base[t];
}

// ---------------- GEMM (2 bf16 splits) + fused LIF scan + borderline flagging ----------
template <int L>
__global__ void __launch_bounds__(256, 2) gemm_lif_kernel(const float* __restrict__ thr_p) {
    constexpr int KTOT = (L == 0) ? D0 : D1;
    constexpr int NC   = KTOT / 64;
    constexpr int JMAX = (L == 0) ? D0 : D2OUT;
    constexpr uint32_t STAGE = 49152u;   // A(16K) + Bh(16K) + Bm(16K)

    extern __shared__ char smem[];
    uint32_t sb = smem_u32(smem);
    int tid = threadIdx.x, wid = tid >> 5, lane = tid & 31;
    int n0 = blockIdx.x * 128, m0 = blockIdx.y * 128;
    int wm = wid >> 1, wn = wid & 1;
    const int mW = wm * 32, nW = wn * 64;

    const __nv_bfloat16* Bs[2];
    if (L == 0) { Bs[0] = g_Bh; Bs[1] = g_Bm; }
    else        { Bs[0] = g_B2h; Bs[1] = g_B2m; }

    auto load_stage = [&](int stage, int kc) {
        uint32_t st = sb + (uint32_t)stage * STAGE;
        int k0 = kc * 64;
#pragma unroll
        for (int u = 0; u < 4; u++) {
            int slot = u * 256 + tid, r = slot >> 3, kk = slot & 7;
            const __nv_bfloat16* gp = g_A + (size_t)(m0 + r) * KTOT + k0 + kk * 8;
            uint32_t off = (uint32_t)(r * 128 + kk * 16);
            CP_ASYNC16(st + SWZ128(off), gp);
        }
#pragma unroll
        for (int s = 0; s < 2; s++) {
            uint32_t bb = st + 16384u * (1 + s);
#pragma unroll
            for (int u = 0; u < 4; u++) {
                int slot = u * 256 + tid, r = slot >> 3, kk = slot & 7;
                const __nv_bfloat16* gp = Bs[s] + (size_t)(n0 + r) * KTOT + k0 + kk * 8;
                uint32_t off = (uint32_t)(r * 128 + kk * 16);
                CP_ASYNC16(bb + SWZ128(off), gp);
            }
        }
        CP_COMMIT();
    };

    float acc[2][8][4];
#pragma unroll
    for (int a = 0; a < 2; a++)
#pragma unroll
        for (int b = 0; b < 8; b++)
#pragma unroll
            for (int c = 0; c < 4; c++) acc[a][b][c] = 0.f;

    int q = lane >> 3, w8 = lane & 7;

    load_stage(0, 0);
#pragma unroll 1
    for (int c = 0; c < NC; c++) {
        if (c + 1 < NC) { load_stage((c + 1) & 1, c + 1); CP_WAIT1(); }
        else            { CP_WAIT0(); }
        __syncthreads();

        uint32_t st = sb + (uint32_t)(c & 1) * STAGE;
#pragma unroll
        for (int ks = 0; ks < 4; ks++) {
            uint32_t af[2][4];
#pragma unroll
            for (int mf = 0; mf < 2; mf++) {
                int row = mW + mf * 16 + w8 + (q & 1) * 8;
                int colb = ks * 32 + (q >> 1) * 16;
                LDSM4(af[mf][0], af[mf][1], af[mf][2], af[mf][3],
                      st + SWZ128((uint32_t)(row * 128 + colb)));
            }
#pragma unroll
            for (int s = 0; s < 2; s++) {
                uint32_t bbase = st + 16384u * (1 + s);
#pragma unroll
                for (int nfp = 0; nfp < 4; nfp++) {
                    uint32_t b0, b1, b2, b3;
                    int row = nW + nfp * 16 + w8 + (q >> 1) * 8;
                    int colb = ks * 32 + (q & 1) * 16;
                    LDSM4(b0, b1, b2, b3, bbase + SWZ128((uint32_t)(row * 128 + colb)));
                    MMA16816(acc[0][2 * nfp + 0], af[0], b0, b1);
                    MMA16816(acc[0][2 * nfp + 1], af[0], b2, b3);
                    MMA16816(acc[1][2 * nfp + 0], af[1], b0, b1);
                    MMA16816(acc[1][2 * nfp + 1], af[1], b2, b3);
                }
            }
        }
        __syncthreads();
    }

    // ---- epilogue: transpose C through padded smem tile, LIF scan + gap flag ----
    float* ct = (float*)smem;                         // [128][129] fp32 (66 KB < 96 KB)
#pragma unroll
    for (int mf = 0; mf < 2; mf++)
#pragma unroll
        for (int nf = 0; nf < 8; nf++) {
            int row = mW + mf * 16 + (lane >> 2);
            int col = nW + nf * 8 + 2 * (lane & 3);
            ct[row * 129 + col]           = acc[mf][nf][0];
            ct[row * 129 + col + 1]       = acc[mf][nf][1];
            ct[(row + 8) * 129 + col]     = acc[mf][nf][2];
            ct[(row + 8) * 129 + col + 1] = acc[mf][nf][3];
        }
    __syncthreads();

    float thr = *thr_p;
    int* cnt_out = (L == 0) ? g_cnt0 : g_cnt2;
    unsigned char* flag_out = (L == 0) ? g_flag0 : g_flag2;
#pragma unroll
    for (int pp = 0; pp < 2; pp++) {
        int p = pp * 256 + tid;
        int bl = p >> 7, j = p & 127;
        float memb = 0.f, ming = 1e30f;
        int cnt = 0;
#pragma unroll
        for (int t = 0; t < TT; t++) {
            memb += ct[(bl * 32 + t) * 129 + j];
            float g = fabsf(memb - thr);
            if (g < ming) ming = g;
            if (memb > thr) { memb -= thr; cnt++; }
        }
        int bglob = blockIdx.y * 4 + bl;
        int jglob = n0 + j;
        if (jglob < JMAX) {
            cnt_out[(size_t)bglob * JMAX + jglob] = cnt;
            flag_out[(size_t)bglob * JMAX + jglob] = (ming < DELTA) ? 1 : 0;
        }
    }
}

// ---------------- exact fix-up: replicate R1's bit-exact scalar path for flagged entries ----
template <int L>
__global__ void fixup_kernel(const float* __restrict__ w, const float* __restrict__ thr_p) {
    constexpr int K    = (L == 0) ? D0 : D1;
    constexpr int JMAX = (L == 0) ? D0 : D2OUT;
    __shared__ uint32_t spat[33];
    int tid = threadIdx.x;
    if (tid < 33) spat[tid] = pattern_mask(tid);
    __syncthreads();

    int b = blockIdx.y;
    int j = blockIdx.x * 256 + tid;
    if (j >= JMAX) return;
    const unsigned char* flag = (L == 0) ? g_flag0 : g_flag2;
    if (!flag[(size_t)b * JMAX + j]) return;

    const uint32_t* po = ((L == 0) ? g_ord0 : g_ord2) + b * K;
    const int*      sg = ((L == 0) ? g_seg0 : g_seg2) + b * 34;
    const float* wrow = w + (size_t)j * K;

    float I[TT];
#pragma unroll
    for (int t = 0; t < TT; t++) I[t] = 0.f;

#pragma unroll 1
    for (int n = 1; n < 33; n++) {
        int s = sg[n], e = sg[n + 1];
        if (s >= e) continue;
        float a0 = 0.f, a1 = 0.f, a2 = 0.f, a3 = 0.f;
        int k = s;
        float p0 = 0.f, p1 = 0.f, p2 = 0.f, p3 = 0.f;
        if (k + 4 <= e) {
            p0 = wrow[po[k]]; p1 = wrow[po[k + 1]];
            p2 = wrow[po[k + 2]]; p3 = wrow[po[k + 3]];
        }
#pragma unroll 1
        for (; k + 4 <= e; ) {
            float c0 = p0, c1 = p1, c2 = p2, c3 = p3;
            int kn = k + 4;
            if (kn + 4 <= e) {
                p0 = wrow[po[kn]]; p1 = wrow[po[kn + 1]];
                p2 = wrow[po[kn + 2]]; p3 = wrow[po[kn + 3]];
            }
            a0 += c0; a1 += c1; a2 += c2; a3 += c3;   // R1 add order
            k = kn;
        }
        for (; k < e; k++) a0 += wrow[po[k]];
        float acc = (a0 + a1) + (a2 + a3);
        uint32_t m = spat[n];
#pragma unroll
        for (int t = 0; t < TT; t++)
            if ((m >> t) & 1u) I[t] += acc;
    }

    float thr = *thr_p;
    float memb = 0.f;
    int cnt = 0;
#pragma unroll
    for (int t = 0; t < TT; t++) {
        memb += I[t];
        if (memb > thr) { memb -= thr; cnt++; }
    }
    if (L == 0) g_cnt0[b * D0 + j] = cnt; else g_cnt2[b * D2OUT + j] = cnt;
}

// ---------------- pooling + layer-1 re-encoding (exact integer/pow2 arithmetic) ----------------
__global__ void mid_kernel(const int* __restrict__ idx1) {
    int b = blockIdx.x, p = threadIdx.x;
    int ch = p >> 4, oh = (p >> 2) & 3, ow = p & 3;
    int c = 0;
#pragma unroll
    for (int dh = 0; dh < 2; dh++)
#pragma unroll
        for (int dw = 0; dw < 2; dw++) {
            int k = ch * 64 + (2 * oh + dh) * 8 + (2 * ow + dw);
            c += g_cnt0[b * D0 + idx1[k]];
        }
    g_N1[b * D1 + p] = (unsigned char)__float2int_rn((float)c * 0.25f);
}

// ---------------- output gather ----------------
__global__ void out_kernel(const int* __restrict__ idx_out, float* __restrict__ out) {
    int b = blockIdx.x, j = threadIdx.x;
    if (j < D2OUT) out[b * D2OUT + j] = (float)g_cnt2[b * D2OUT + idx_out[j]];
}

// ---------------- launch ----------------
extern "C" void kernel_launch(void* const* d_in, const int* in_sizes, int n_in,
                              void* d_out, int out_size) {
    (void)in_sizes; (void)n_in; (void)out_size;
    const float* x       = (const float*)d_in[0];
    const float* w0      = (const float*)d_in[1];
    const float* t0      = (const float*)d_in[2];
    const float* w2      = (const float*)d_in[3];
    const float* t2      = (const float*)d_in[4];
    const int*   idx0    = (const int*)d_in[5];
    const int*   idx1    = (const int*)d_in[6];
    const int*   idx2    = (const int*)d_in[7];
    const int*   idx_out = (const int*)d_in[8];
    float* out = (float*)d_out;

    const int SMEM_TOTAL = 2 * 49152;   // 96 KB -> 2 CTAs/SM
    cudaFuncSetAttribute(gemm_lif_kernel<0>, cudaFuncAttributeMaxDynamicSharedMemorySize, SMEM_TOTAL);
    cudaFuncSetAttribute(gemm_lif_kernel<1>, cudaFuncAttributeMaxDynamicSharedMemorySize, SMEM_TOTAL);

    split0_kernel<<<(int)(((size_t)D0 * D0) / 256), 256>>>(w0);
    split2_kernel<<<(D2OUT * D1) / 256, 256>>>(w2);

    buildA0_kernel<<<dim3(D0 / 256, BB), 256>>>(x, idx0);
    sort_kernel<D0><<<BB, 128>>>(x, idx0);
    gemm_lif_kernel<0><<<dim3(D0 / 128, MROWS / 128), 256, SMEM_TOTAL>>>(t0);
    fixup_kernel<0><<<dim3(D0 / 256, BB), 256>>>(w0, t0);

    mid_kernel<<<BB, D1>>>(idx1);
    buildA2_kernel<<<dim3(D1 / 256, BB), 256>>>(idx2);
    sort_kernel<D1><<<BB, 128>>>(x, idx2);
    gemm_lif_kernel<1><<<dim3(D1 / 128, MROWS / 128), 256, SMEM_TOTAL>>>(t2);
    fixup_kernel<1><<<dim3(4, BB), 256>>>(w2, t2);

    out_kernel<<<BB, 1024>>>(idx_out, out);
}